// round 17
// baseline (speedup 1.0000x reference)
#include <cuda_runtime.h>
#include <cuda_bf16.h>

// FINAL FORM — R15 configuration (best kernel time of 9 variants: 58.46us,
// DRAM 86.4%, 6844 GB/s) with the free cond-sub retained. R16 proved
// block=512 regresses (occ 79%, DRAM 83.6%); 256 is the launch-shape optimum.
//
// Established model (R2-R16 ablations):
//   * traffic floor 400 MB: z_1 fetched at 64B HBM granule (256 MB, half
//     wasted but unavoidable), dir one sector/row (128 MB), out 16 MB.
//   * DRAM busy 86.4% == controller efficiency ceiling for this mix; MLP /
//     occupancy / batching / persistence / hints / prefetch all within noise
//     or worse.
//   * __ldg beats __ldcs; plain multi-wave launch beats persistent grid;
//     dependent 4B gather beats dir-row preload.

__global__ __launch_bounds__(256) void slope_valuation_kernel(
    const float4* __restrict__ z4,   // z_1 as float4 (4 per 16-float row)
    const float*  __restrict__ z,    // z_1 scalar view
    const float*  __restrict__ dir,  // [B, 8]
    float*        __restrict__ out,  // [B]
    int n)
{
    int i = blockIdx.x * blockDim.x + threadIdx.x;
    if (i >= n) return;

    const float* dir_row = dir + (size_t)i * 8;

    // Fire-and-forget: dir line DRAM->L2 while the z load is in flight.
    asm volatile("prefetch.global.L2 [%0];" :: "l"(dir_row));

    // cols 0..3 (line, lx, ly, rx): one 16B load at row base
    float4 v = __ldg(&z4[(size_t)i * 4]);
    // col 4 (ry): same 32B sector
    float ry = __ldg(&z[(size_t)i * 16 + 4]);

    float dx = v.w - v.y;
    float dy = -(ry - v.z);

    float phi = atan2f(dy, dx) * 57.29577951308232f;
    if (phi < 0.0f) phi += 360.0f;

    // pcs = (90 + int(phi)) % 360 ; int(phi) in [0,360) -> single cond-sub
    int pcs = 90 + (int)phi;
    if (pcs >= 360) pcs -= 360;

    int zone = ((pcs + 11) / 22) & 7;   // area_angle=22, half=11 (exact)

    float picked = __ldg(&dir_row[zone]);   // L2 hit after prefetch
    out[i] = (v.x != 0.0f) ? picked : 0.0f;
}

extern "C" void kernel_launch(void* const* d_in, const int* in_sizes, int n_in,
                              void* d_out, int out_size)
{
    const float* z_1 = (const float*)d_in[0];   // [B,16] fp32
    const float* dir = (const float*)d_in[1];   // [B,8]  fp32
    float* out = (float*)d_out;                 // [B]    fp32

    int n = in_sizes[0] / 16;                   // B rows

    int threads = 256;
    int blocks = (n + threads - 1) / threads;
    slope_valuation_kernel<<<blocks, threads>>>(
        (const float4*)z_1, z_1, dir, out, n);
}